// round 10
// baseline (speedup 1.0000x reference)
#include <cuda_runtime.h>
#include <math.h>

// Shape (4, 2, 16, 512, 512) fp32
#define R       8                  // B*C channels
#define NS      4194304            // spatial elems per channel
#define NS4     (NS / 4)           // float4 per channel
#define NBINS   256
#define TPB     128
#define NW      (TPB / 32)         // 4 warps
#define CHUNK   4                  // float4 per load batch
#define BPC     128                // blocks per channel
#define GRID    (R * BPC)          // 1024 blocks, all resident at 7 CTAs/SM
#define IT      16                 // TPB*CHUNK*IT == 8192 float4 per block slice
#define SLICE   (TPB * CHUNK * IT) // 8192

// ------------- scratch: static init == post-reset state --------------------
__device__ unsigned int g_minkey[R] = {0xFFFFFFFFu,0xFFFFFFFFu,0xFFFFFFFFu,0xFFFFFFFFu,
                                       0xFFFFFFFFu,0xFFFFFFFFu,0xFFFFFFFFu,0xFFFFFFFFu};
__device__ unsigned int       g_maxkey[R];          // 0
__device__ unsigned int       g_hist[R][NBINS];     // 0
__device__ float              g_thr[R];
__device__ double             g_msum[R], g_tot[R], g_inter[R], g_ssum[R];
__device__ unsigned long long g_fg[R];
__device__ unsigned int       g_cnt_mm[R], g_cnt_hist[R], g_thr_ready[R];
__device__ unsigned int       g_cnt_main;

__device__ __forceinline__ unsigned int fkey(float f) {
    unsigned int u = __float_as_uint(f);
    return (u & 0x80000000u) ? ~u : (u | 0x80000000u);
}
__device__ __forceinline__ float ikey(unsigned int k) {
    unsigned int u = (k & 0x80000000u) ? (k & 0x7FFFFFFFu) : ~k;
    return __uint_as_float(u);
}
__device__ __forceinline__ float bin_center(float lo, float span, int i) {
    float t0 = (float)i       * (1.0f / 256.0f);
    float t1 = (float)(i + 1) * (1.0f / 256.0f);
    float e0 = __fadd_rn(lo, __fmul_rn(span, t0));
    float e1 = __fadd_rn(lo, __fmul_rn(span, t1));
    return __fmul_rn(__fadd_rn(e0, e1), 0.5f);
}

// tid0 polls (volatile -> L2), block released via syncthreads, fence = acquire
__device__ __forceinline__ void gate(volatile unsigned int* p, unsigned int v) {
    if (threadIdx.x == 0) { while (*p < v) __nanosleep(64); }
    __syncthreads();
    __threadfence();
}

// =================== ONE persistent kernel, three phases ===================
__global__ __launch_bounds__(TPB, 7)
void k_spot(const float4* __restrict__ pred, const float4* __restrict__ tgt,
            float* __restrict__ out) {
    const int tid  = threadIdx.x;
    const int bid  = blockIdx.x;
    const int c    = bid >> 7;          // channel
    const int blk  = bid & (BPC - 1);   // block within channel
    const int w    = tid >> 5, lane = tid & 31;
    const size_t s0 = (size_t)c * NS4 + (size_t)blk * SLICE;  // my slice

    __shared__ float  sred[NW];
    __shared__ float  sred2[NW];
    __shared__ unsigned int sh[NW][NBINS];
    __shared__ float  s_lo, s_span_safe, s_span_raw;

    // ---------------- phase 1: min/max over my slice (forward) ----------------
    {
        const float4* base = tgt + s0 + tid;
        float lo0 = INFINITY, hi0 = -INFINITY, lo1 = INFINITY, hi1 = -INFINITY;
        #pragma unroll
        for (int it = 0; it < IT; it++) {
            float4 V[CHUNK];
            const int ioff = it * (TPB * CHUNK);
            #pragma unroll
            for (int k = 0; k < CHUNK; k++) V[k] = base[ioff + k * TPB];
            #pragma unroll
            for (int k = 0; k < CHUNK; k++) {
                float l = fminf(fminf(V[k].x, V[k].y), fminf(V[k].z, V[k].w));
                float h = fmaxf(fmaxf(V[k].x, V[k].y), fmaxf(V[k].z, V[k].w));
                if (k & 1) { lo1 = fminf(lo1, l); hi1 = fmaxf(hi1, h); }
                else       { lo0 = fminf(lo0, l); hi0 = fmaxf(hi0, h); }
            }
        }
        float lo = fminf(lo0, lo1), hi = fmaxf(hi0, hi1);
        for (int o = 16; o > 0; o >>= 1) {
            lo = fminf(lo, __shfl_down_sync(0xFFFFFFFFu, lo, o));
            hi = fmaxf(hi, __shfl_down_sync(0xFFFFFFFFu, hi, o));
        }
        if (lane == 0) { sred[w] = lo; sred2[w] = hi; }
        __syncthreads();
        if (tid == 0) {
            float l = sred[0], h = sred2[0];
            #pragma unroll
            for (int i = 1; i < NW; i++) { l = fminf(l, sred[i]); h = fmaxf(h, sred2[i]); }
            atomicMin(&g_minkey[c], fkey(l));
            atomicMax(&g_maxkey[c], fkey(h));
            __threadfence();
            atomicAdd(&g_cnt_mm[c], 1u);
        }
    }
    gate(&g_cnt_mm[c], BPC);            // all blocks of channel c done minmax

    // zero warp-hists while waiting-adjacent
    for (int i = tid; i < NW * NBINS; i += TPB) ((unsigned int*)sh)[i] = 0u;
    if (tid == 0) {
        float lo = ikey(g_minkey[c]);
        float hi = ikey(g_maxkey[c]);
        float span = __fsub_rn(hi, lo);
        s_lo = lo; s_span_raw = span;
        s_span_safe = (span > 0.0f) ? span : 1.0f;
    }
    __syncthreads();
    const float lo = s_lo, span = s_span_safe;

    // ------- phase 2: histogram over my slice (REVERSE: freshest-L2 first) ----
    {
        const float4* rtop = tgt + s0 + (SLICE - 1);
        #pragma unroll
        for (int it = 0; it < IT; it++) {
            float4 V[CHUNK];
            const int ibase = it * (TPB * CHUNK) + tid;
            #pragma unroll
            for (int k = 0; k < CHUNK; k++)
                V[k] = rtop[-(ibase + k * TPB)];
            #pragma unroll
            for (int k = 0; k < CHUNK; k++) {
                #pragma unroll
                for (int j = 0; j < 4; j++) {
                    float x = (j == 0) ? V[k].x : (j == 1) ? V[k].y
                            : (j == 2) ? V[k].z : V[k].w;
                    float q = __fmul_rn(__fdiv_rn(__fsub_rn(x, lo), span), 256.0f);
                    int b = (int)q;
                    b = min(max(b, 0), NBINS - 1);
                    atomicAdd(&sh[w][b], 1u);
                }
            }
        }
        __syncthreads();
        for (int bin = tid; bin < NBINS; bin += TPB) {
            unsigned int s = 0;
            #pragma unroll
            for (int k = 0; k < NW; k++) s += sh[k][bin];
            if (s) atomicAdd(&g_hist[c][bin], s);
        }
        __threadfence();
        __shared__ bool is_last;
        if (tid == 0)
            is_last = (atomicAdd(&g_cnt_hist[c], 1u) == (unsigned)(BPC - 1));
        __syncthreads();

        // ---- last hist block of this channel: Otsu (128 thr, 2 bins each) ----
        if (is_last) {
            __shared__ float s_h[NBINS], s_hm[NBINS], s_ctr[NBINS];
            __shared__ float s_cs[NBINS], s_cm[NBINS];
            __shared__ float rv[TPB]; __shared__ int ri[TPB];
            const float span_raw = s_span_raw;
            #pragma unroll
            for (int hb = 0; hb < 2; hb++) {
                int b = tid + hb * TPB;
                float h   = (float)__ldcg(&g_hist[c][b]);
                float ctr = bin_center(lo, span_raw, b);
                s_h[b] = h; s_ctr[b] = ctr; s_hm[b] = __fmul_rn(h, ctr);
            }
            __syncthreads();
            if (tid == 0) {   // sequential fp32 cumsum (reference order)
                float cs = 0.0f, cm = 0.0f;
                #pragma unroll
                for (int i = 0; i < NBINS; i++) {
                    cs = __fadd_rn(cs, s_h[i]);
                    cm = __fadd_rn(cm, s_hm[i]);
                    s_cs[i] = cs; s_cm[i] = cm;
                }
            }
            __syncthreads();
            const float total = s_cs[NBINS - 1];
            const float gmean = s_cm[NBINS - 1];
            float bv[2]; int biv[2];
            #pragma unroll
            for (int hb = 0; hb < 2; hb++) {
                int b = tid + hb * TPB;
                float cs = s_cs[b], cm = s_cm[b];
                float A  = __fsub_rn(__fmul_rn(cm, total), __fmul_rn(gmean, cs));
                float dn = __fadd_rn(__fmul_rn(cs, __fsub_rn(total, cs)), 1e-10f);
                bv[hb] = __fdiv_rn(__fmul_rn(A, A), dn);
                biv[hb] = b;
            }
            // combine my two bins (tie -> lower index = bv[0])
            if (bv[1] > bv[0]) { bv[0] = bv[1]; biv[0] = biv[1]; }
            rv[tid] = bv[0]; ri[tid] = biv[0];
            __syncthreads();
            for (int s = TPB / 2; s > 0; s >>= 1) {
                if (tid < s) {
                    if (rv[tid + s] > rv[tid] ||
                        (rv[tid + s] == rv[tid] && ri[tid + s] < ri[tid])) {
                        rv[tid] = rv[tid + s]; ri[tid] = ri[tid + s];
                    }
                }
                __syncthreads();
            }
            if (tid == 0) {
                g_thr[c] = (span_raw > 0.0f) ? s_ctr[ri[0]] : lo;
                __threadfence();
                atomicExch(&g_thr_ready[c], 1u);
            }
        }
    }
    gate(&g_thr_ready[c], 1u);          // threshold ready for channel c

    // ---------------- phase 3: fused main reductions (forward) ---------------
    const float thr = __ldcg(&g_thr[c]);
    {
        const float4* pb = pred + s0 + tid;
        const float4* tb = tgt  + s0 + tid;
        float msum0 = 0.f, tot0 = 0.f, int0 = 0.f, ss0 = 0.f;
        float msum1 = 0.f, tot1 = 0.f, int1 = 0.f, ss1 = 0.f;
        int fg = 0;
        #pragma unroll
        for (int it = 0; it < IT; it++) {
            float4 P[CHUNK], T[CHUNK];
            const int ioff = it * (TPB * CHUNK);
            #pragma unroll
            for (int k = 0; k < CHUNK; k++) {   // 8 LDG.128 back-to-back
                P[k] = pb[ioff + k * TPB];
                T[k] = tb[ioff + k * TPB];
            }
            #pragma unroll
            for (int k = 0; k < CHUNK; k++) {
                #pragma unroll
                for (int j = 0; j < 4; j++) {
                    float p = (j == 0) ? P[k].x : (j == 1) ? P[k].y
                            : (j == 2) ? P[k].z : P[k].w;
                    float t = (j == 0) ? T[k].x : (j == 1) ? T[k].y
                            : (j == 2) ? T[k].z : T[k].w;
                    bool m = (t >= thr);
                    float d  = p - t;
                    float se = d * d;
                    float ax  = fabsf(p);
                    float num = p - (-0.95f) * p;                 // 1.95*x
                    float den = (-0.95f - (-1.9f) * ax) + 1.0f;   // 0.05+1.9|x|
                    float sp  = __saturatef(__fdividef(num, den));
                    float sem = m ? se : 0.0f;
                    float spm = m ? sp : 0.0f;
                    fg += m;
                    if (k & 1) { tot1 += se; msum1 += sem; ss1 += sp; int1 += spm; }
                    else       { tot0 += se; msum0 += sem; ss0 += sp; int0 += spm; }
                }
            }
        }
        float msum = msum0 + msum1, tot = tot0 + tot1;
        float inter = int0 + int1,  ssum = ss0 + ss1;
        for (int o = 16; o > 0; o >>= 1) {
            msum  += __shfl_down_sync(0xFFFFFFFFu, msum,  o);
            tot   += __shfl_down_sync(0xFFFFFFFFu, tot,   o);
            inter += __shfl_down_sync(0xFFFFFFFFu, inter, o);
            ssum  += __shfl_down_sync(0xFFFFFFFFu, ssum,  o);
            fg    += __shfl_down_sync(0xFFFFFFFFu, fg,    o);
        }
        __shared__ float  t0s[NW], t1s[NW], t2s[NW], t3s[NW];
        __shared__ int    t4s[NW];
        if (lane == 0) { t0s[w]=msum; t1s[w]=tot; t2s[w]=inter; t3s[w]=ssum; t4s[w]=fg; }
        __syncthreads();
        __shared__ bool last_main;
        if (tid == 0) {
            double a=0, b=0, cI=0, dS=0; long long f=0;
            #pragma unroll
            for (int k = 0; k < NW; k++) { a+=t0s[k]; b+=t1s[k]; cI+=t2s[k]; dS+=t3s[k]; f+=t4s[k]; }
            atomicAdd(&g_msum[c],  a);
            atomicAdd(&g_tot[c],   b);
            atomicAdd(&g_inter[c], cI);
            atomicAdd(&g_ssum[c],  dS);
            atomicAdd(&g_fg[c], (unsigned long long)f);
            __threadfence();
            last_main = (atomicAdd(&g_cnt_main, 1u) == (unsigned)(GRID - 1));
        }
        __syncthreads();
        if (!last_main) return;
    }

    // ---- globally-last block: combine to scalar + self-clean -----------------
    if (tid == 0) {
        double mse_sum = 0.0, dice_sum = 0.0;
        int nmask = 0;
        for (int ch = 0; ch < R; ch++) {
            double fgc = (double)__ldcg(&g_fg[ch]);
            bool has = fgc > 0.0;
            double cmse = has ? __ldcg(&g_msum[ch]) / (fgc + 1e-6)
                              : __ldcg(&g_tot[ch]) / (double)NS;
            mse_sum += cmse;
            if (has) {
                dice_sum += 1.0 - 2.0 * __ldcg(&g_inter[ch]) /
                                        (__ldcg(&g_ssum[ch]) + fgc + 1e-6);
                nmask++;
            }
        }
        double masked_mse = mse_sum / (double)R;
        double dice = (nmask > 0) ? dice_sum / (double)nmask : 0.0;
        out[0] = (float)(0.5 * masked_mse + 0.5 * dice);
    }
    __syncthreads();
    for (int i = tid; i < R * NBINS; i += TPB)
        ((unsigned int*)g_hist)[i] = 0u;
    if (tid < R) {
        g_minkey[tid] = 0xFFFFFFFFu;
        g_maxkey[tid] = 0u;
        g_msum[tid] = 0.0; g_tot[tid] = 0.0; g_inter[tid] = 0.0; g_ssum[tid] = 0.0;
        g_fg[tid] = 0ull;
        g_thr[tid] = 0.0f;
        g_cnt_mm[tid] = 0u; g_cnt_hist[tid] = 0u; g_thr_ready[tid] = 0u;
    }
    if (tid == R) g_cnt_main = 0u;
}

// ---------------- launch ----------------
extern "C" void kernel_launch(void* const* d_in, const int* in_sizes, int n_in,
                              void* d_out, int out_size) {
    const float4* pred = (const float4*)d_in[0];
    const float4* tgt  = (const float4*)d_in[1];
    float* out = (float*)d_out;
    k_spot<<<GRID, TPB>>>(pred, tgt, out);
}

// round 11
// speedup vs baseline: 2.2943x; 2.2943x over previous
#include <cuda_runtime.h>
#include <math.h>

// Shape (4, 2, 16, 512, 512) fp32
#define R       8                  // B*C channels
#define GR      4                  // channels per group (67MB target slice fits L2)
#define NS      4194304            // spatial elems per channel
#define NS4     (NS / 4)           // float4 per channel
#define NBINS   256
#define TPB     256
#define CHUNK   4                  // float4 per batch

#define BPC_MM  1024               // minmax: 1 batch/block (R8 measured-good)
#define IT_H    4
#define BPC_H   256                // hist: 4 batches/block (R8 measured-good)
#define IT_M    8
#define BPC_M   128                // main: 8 batches/block (R8 measured-good)

// ------------- scratch: static init == post-reset state --------------------
__device__ unsigned int g_minkey[R] = {0xFFFFFFFFu,0xFFFFFFFFu,0xFFFFFFFFu,0xFFFFFFFFu,
                                       0xFFFFFFFFu,0xFFFFFFFFu,0xFFFFFFFFu,0xFFFFFFFFu};
__device__ unsigned int       g_maxkey[R];          // 0
__device__ unsigned int       g_hist[R][NBINS];     // 0
__device__ float              g_thr[R];
__device__ double             g_msum[R], g_tot[R], g_inter[R], g_ssum[R];
__device__ unsigned long long g_fg[R];
__device__ unsigned int       g_cnt_hist[R], g_cnt_main;

__device__ __forceinline__ unsigned int fkey(float f) {
    unsigned int u = __float_as_uint(f);
    return (u & 0x80000000u) ? ~u : (u | 0x80000000u);
}
__device__ __forceinline__ float ikey(unsigned int k) {
    unsigned int u = (k & 0x80000000u) ? (k & 0x7FFFFFFFu) : ~k;
    return __uint_as_float(u);
}
__device__ __forceinline__ float bin_center(float lo, float span, int i) {
    float t0 = (float)i       * (1.0f / 256.0f);
    float t1 = (float)(i + 1) * (1.0f / 256.0f);
    float e0 = __fadd_rn(lo, __fmul_rn(span, t0));
    float e1 = __fadd_rn(lo, __fmul_rn(span, t1));
    return __fmul_rn(__fadd_rn(e0, e1), 0.5f);
}

// --------- kernel 1: per-channel-group min/max (R8 shape, c0 offset) -------
__global__ __launch_bounds__(TPB) void k_minmax(const float4* __restrict__ tgt,
                                                int c0) {
    const int c = c0 + blockIdx.y;
    const int tid = threadIdx.x;
    const float4* base = tgt + (size_t)c * NS4
                             + (size_t)blockIdx.x * (TPB * CHUNK) + tid;
    float4 V[CHUNK];
    #pragma unroll
    for (int k = 0; k < CHUNK; k++) V[k] = base[k * TPB];

    float lo0 = INFINITY, hi0 = -INFINITY, lo1 = INFINITY, hi1 = -INFINITY;
    #pragma unroll
    for (int k = 0; k < CHUNK; k++) {
        float l = fminf(fminf(V[k].x, V[k].y), fminf(V[k].z, V[k].w));
        float h = fmaxf(fmaxf(V[k].x, V[k].y), fmaxf(V[k].z, V[k].w));
        if (k & 1) { lo1 = fminf(lo1, l); hi1 = fmaxf(hi1, h); }
        else       { lo0 = fminf(lo0, l); hi0 = fmaxf(hi0, h); }
    }
    float lo = fminf(lo0, lo1), hi = fmaxf(hi0, hi1);
    for (int o = 16; o > 0; o >>= 1) {
        lo = fminf(lo, __shfl_down_sync(0xFFFFFFFFu, lo, o));
        hi = fmaxf(hi, __shfl_down_sync(0xFFFFFFFFu, hi, o));
    }
    __shared__ float slo[8], shi[8];
    int w = tid >> 5, lane = tid & 31;
    if (lane == 0) { slo[w] = lo; shi[w] = hi; }
    __syncthreads();
    if (tid == 0) {
        float l = slo[0], h = shi[0];
        for (int i = 1; i < 8; i++) { l = fminf(l, slo[i]); h = fmaxf(h, shi[i]); }
        atomicMin(&g_minkey[c], fkey(l));
        atomicMax(&g_maxkey[c], fkey(h));
    }
}

// ----- kernel 2: per-group histogram (reads L2-hot slice) + fused Otsu -----
__global__ __launch_bounds__(TPB) void k_hist(const float4* __restrict__ tgt,
                                              int c0) {
    const int c = c0 + blockIdx.y;
    __shared__ unsigned int sh[8][NBINS];   // per-warp sub-histograms
    __shared__ float s_lo, s_span_safe, s_span_raw;
    int tid = threadIdx.x, w = tid >> 5;
    for (int i = tid; i < 8 * NBINS; i += TPB)
        ((unsigned int*)sh)[i] = 0u;
    if (tid == 0) {
        float lo = ikey(g_minkey[c]);
        float hi = ikey(g_maxkey[c]);
        float span = __fsub_rn(hi, lo);
        s_lo = lo;
        s_span_raw = span;
        s_span_safe = (span > 0.0f) ? span : 1.0f;
    }
    __syncthreads();
    const float lo = s_lo, span = s_span_safe;

    const float4* base = tgt + (size_t)c * NS4;
    const int bbase = blockIdx.x * (TPB * CHUNK * IT_H) + tid;
    #pragma unroll
    for (int it = 0; it < IT_H; it++) {
        float4 V[CHUNK];
        const int ibase = bbase + it * (TPB * CHUNK);
        #pragma unroll
        for (int k = 0; k < CHUNK; k++)        // 4 LDG.128 back-to-back
            V[k] = base[ibase + k * TPB];
        #pragma unroll
        for (int k = 0; k < CHUNK; k++) {
            #pragma unroll
            for (int j = 0; j < 4; j++) {
                float x = (j == 0) ? V[k].x : (j == 1) ? V[k].y
                        : (j == 2) ? V[k].z : V[k].w;
                float q = __fmul_rn(__fdiv_rn(__fsub_rn(x, lo), span), 256.0f);
                int b = (int)q;
                b = min(max(b, 0), NBINS - 1);
                atomicAdd(&sh[w][b], 1u);
            }
        }
    }
    __syncthreads();
    {
        unsigned int s = 0;
        #pragma unroll
        for (int k = 0; k < 8; k++) s += sh[k][tid];
        if (s) atomicAdd(&g_hist[c][tid], s);
    }

    // ---- last block of this channel computes the Otsu threshold ----
    __threadfence();
    __shared__ bool is_last;
    if (tid == 0)
        is_last = (atomicAdd(&g_cnt_hist[c], 1u) == (unsigned)(BPC_H - 1));
    __syncthreads();
    if (!is_last) return;

    __shared__ float s_h[NBINS], s_hm[NBINS], s_ctr[NBINS];
    __shared__ float s_cs[NBINS], s_cm[NBINS];
    __shared__ float rv[NBINS]; __shared__ int ri[NBINS];

    const float span_raw = s_span_raw;
    float h   = (float)__ldcg(&g_hist[c][tid]);
    float ctr = bin_center(lo, span_raw, tid);
    s_h[tid] = h; s_ctr[tid] = ctr; s_hm[tid] = __fmul_rn(h, ctr);
    __syncthreads();

    if (tid == 0) {   // sequential fp32 cumsum (matches reference order)
        float cs = 0.0f, cm = 0.0f;
        #pragma unroll
        for (int i = 0; i < NBINS; i++) {
            cs = __fadd_rn(cs, s_h[i]);
            cm = __fadd_rn(cm, s_hm[i]);
            s_cs[i] = cs; s_cm[i] = cm;
        }
    }
    __syncthreads();
    const float total = s_cs[NBINS - 1];
    const float gmean = s_cm[NBINS - 1];

    float cs = s_cs[tid], cm = s_cm[tid];
    float A  = __fsub_rn(__fmul_rn(cm, total), __fmul_rn(gmean, cs));
    float dn = __fadd_rn(__fmul_rn(cs, __fsub_rn(total, cs)), 1e-10f);
    float iv = __fdiv_rn(__fmul_rn(A, A), dn);

    rv[tid] = iv; ri[tid] = tid;
    __syncthreads();
    for (int s = NBINS / 2; s > 0; s >>= 1) {   // argmax, first-index tie-break
        if (tid < s) {
            if (rv[tid + s] > rv[tid] ||
                (rv[tid + s] == rv[tid] && ri[tid + s] < ri[tid])) {
                rv[tid] = rv[tid + s]; ri[tid] = ri[tid + s];
            }
        }
        __syncthreads();
    }
    if (tid == 0)
        g_thr[c] = (span_raw > 0.0f) ? s_ctr[ri[0]] : lo;
}

// ---- kernel 3: fused main reductions (R8 shape; ch 7..0 for L2 hits) ------
__global__ __launch_bounds__(TPB) void k_main(const float4* __restrict__ pred,
                                              const float4* __restrict__ tgt,
                                              float* __restrict__ out) {
    const int c = (R - 1) - blockIdx.y;   // ch7 first: tgt ch4-7 still L2-hot
    const int tid = threadIdx.x;
    const float thr = g_thr[c];
    const size_t base = (size_t)c * NS4
                      + (size_t)blockIdx.x * (TPB * CHUNK * IT_M) + tid;
    const float4* pb = pred + base;
    const float4* tb = tgt  + base;

    float msum0 = 0.f, tot0 = 0.f, int0 = 0.f, ss0 = 0.f;
    float msum1 = 0.f, tot1 = 0.f, int1 = 0.f, ss1 = 0.f;
    int fg = 0;

    #pragma unroll
    for (int it = 0; it < IT_M; it++) {
        float4 P[CHUNK], T[CHUNK];
        const int ioff = it * (TPB * CHUNK);
        #pragma unroll
        for (int k = 0; k < CHUNK; k++) {     // 8 LDG.128 back-to-back (MLP 8)
            P[k] = pb[ioff + k * TPB];
            T[k] = tb[ioff + k * TPB];
        }
        #pragma unroll
        for (int k = 0; k < CHUNK; k++) {
            #pragma unroll
            for (int j = 0; j < 4; j++) {
                float p = (j == 0) ? P[k].x : (j == 1) ? P[k].y
                        : (j == 2) ? P[k].z : P[k].w;
                float t = (j == 0) ? T[k].x : (j == 1) ? T[k].y
                        : (j == 2) ? T[k].z : T[k].w;
                bool m = (t >= thr);
                float d  = p - t;
                float se = d * d;
                float ax  = fabsf(p);
                float num = p - (-0.95f) * p;                 // 1.95*x
                float den = (-0.95f - (-1.9f) * ax) + 1.0f;   // 0.05 + 1.9|x|
                float sp  = __saturatef(__fdividef(num, den));
                float sem = m ? se : 0.0f;
                float spm = m ? sp : 0.0f;
                fg += m;
                if (k & 1) { tot1 += se; msum1 += sem; ss1 += sp; int1 += spm; }
                else       { tot0 += se; msum0 += sem; ss0 += sp; int0 += spm; }
            }
        }
    }
    float msum = msum0 + msum1, tot = tot0 + tot1;
    float inter = int0 + int1,  ssum = ss0 + ss1;

    for (int o = 16; o > 0; o >>= 1) {
        msum  += __shfl_down_sync(0xFFFFFFFFu, msum,  o);
        tot   += __shfl_down_sync(0xFFFFFFFFu, tot,   o);
        inter += __shfl_down_sync(0xFFFFFFFFu, inter, o);
        ssum  += __shfl_down_sync(0xFFFFFFFFu, ssum,  o);
        fg    += __shfl_down_sync(0xFFFFFFFFu, fg,    o);
    }
    __shared__ float  s0[8], s1[8], s2[8], s3[8];
    __shared__ int    s4[8];
    int w = tid >> 5, lane = tid & 31;
    if (lane == 0) { s0[w]=msum; s1[w]=tot; s2[w]=inter; s3[w]=ssum; s4[w]=fg; }
    __syncthreads();
    __shared__ bool is_last;
    if (tid == 0) {
        double a=0, b=0, cI=0, dS=0; long long f=0;
        #pragma unroll
        for (int k = 0; k < 8; k++) { a+=s0[k]; b+=s1[k]; cI+=s2[k]; dS+=s3[k]; f+=s4[k]; }
        atomicAdd(&g_msum[c],  a);
        atomicAdd(&g_tot[c],   b);
        atomicAdd(&g_inter[c], cI);
        atomicAdd(&g_ssum[c],  dS);
        atomicAdd(&g_fg[c], (unsigned long long)f);
        __threadfence();
        is_last = (atomicAdd(&g_cnt_main, 1u) == (unsigned)(BPC_M * R - 1));
    }
    __syncthreads();
    if (!is_last) return;

    // ---- globally-last block: combine to scalar ----
    if (tid == 0) {
        double mse_sum = 0.0, dice_sum = 0.0;
        int nmask = 0;
        for (int ch = 0; ch < R; ch++) {
            double fgc = (double)__ldcg(&g_fg[ch]);
            bool has = fgc > 0.0;
            double cmse = has ? __ldcg(&g_msum[ch]) / (fgc + 1e-6)
                              : __ldcg(&g_tot[ch]) / (double)NS;
            mse_sum += cmse;
            if (has) {
                dice_sum += 1.0 - 2.0 * __ldcg(&g_inter[ch]) /
                                        (__ldcg(&g_ssum[ch]) + fgc + 1e-6);
                nmask++;
            }
        }
        double masked_mse = mse_sum / (double)R;
        double dice = (nmask > 0) ? dice_sum / (double)nmask : 0.0;
        out[0] = (float)(0.5 * masked_mse + 0.5 * dice);
    }
    __syncthreads();   // combine reads done before reset below

    // ---- self-clean scratch back to static-init state for next replay ----
    for (int i = tid; i < R * NBINS; i += TPB)
        ((unsigned int*)g_hist)[i] = 0u;
    if (tid < R) {
        g_minkey[tid] = 0xFFFFFFFFu;
        g_maxkey[tid] = 0u;
        g_msum[tid] = 0.0; g_tot[tid] = 0.0; g_inter[tid] = 0.0; g_ssum[tid] = 0.0;
        g_fg[tid] = 0ull;
        g_thr[tid] = 0.0f;
        g_cnt_hist[tid] = 0u;
    }
    if (tid == R) g_cnt_main = 0u;
}

// ---------------- launch: group-wise for L2 reuse --------------------------
extern "C" void kernel_launch(void* const* d_in, const int* in_sizes, int n_in,
                              void* d_out, int out_size) {
    const float4* pred = (const float4*)d_in[0];
    const float4* tgt  = (const float4*)d_in[1];
    float* out = (float*)d_out;

    // group 0 (ch 0-3): minmax then hist while the 67MB slice is L2-resident
    k_minmax<<<dim3(BPC_MM, GR), TPB>>>(tgt, 0);
    k_hist  <<<dim3(BPC_H,  GR), TPB>>>(tgt, 0);
    // group 1 (ch 4-7)
    k_minmax<<<dim3(BPC_MM, GR), TPB>>>(tgt, GR);
    k_hist  <<<dim3(BPC_H,  GR), TPB>>>(tgt, GR);
    // main over all channels, ch7 first (its target slice still L2-hot)
    k_main  <<<dim3(BPC_M,  R), TPB>>>(pred, tgt, out);
}

// round 12
// speedup vs baseline: 2.5745x; 1.1221x over previous
#include <cuda_runtime.h>
#include <math.h>

// Shape (4, 2, 16, 512, 512) fp32
#define R       8                  // B*C channels
#define NS      4194304            // spatial elems per channel
#define NS4     (NS / 4)           // float4 per channel
#define NBINS   256
#define TPB     256
#define CHUNK   4                  // float4 per batch

// R8 measured-good shapes
#define BPC_MM  1024               // minmax: 1 batch/block
#define IT_H    4
#define BPC_H   256                // hist: 4 batches/block
#define IT_M    8
#define BPC_M   128                // main: 8 batches/block -> 1024 blocks, 1 wave @7/SM

// ------------- scratch: static init == post-reset state --------------------
__device__ unsigned int g_minkey[R] = {0xFFFFFFFFu,0xFFFFFFFFu,0xFFFFFFFFu,0xFFFFFFFFu,
                                       0xFFFFFFFFu,0xFFFFFFFFu,0xFFFFFFFFu,0xFFFFFFFFu};
__device__ unsigned int       g_maxkey[R];          // 0
__device__ unsigned int       g_hist[R][NBINS];     // 0
__device__ float              g_thr[R];
__device__ double             g_msum[R], g_inter[R], g_ssum[R];
__device__ unsigned long long g_fg[R];
__device__ unsigned int       g_cnt_hist[R], g_cnt_main;

__device__ __forceinline__ unsigned int fkey(float f) {
    unsigned int u = __float_as_uint(f);
    return (u & 0x80000000u) ? ~u : (u | 0x80000000u);
}
__device__ __forceinline__ float ikey(unsigned int k) {
    unsigned int u = (k & 0x80000000u) ? (k & 0x7FFFFFFFu) : ~k;
    return __uint_as_float(u);
}
__device__ __forceinline__ float bin_center(float lo, float span, int i) {
    float t0 = (float)i       * (1.0f / 256.0f);
    float t1 = (float)(i + 1) * (1.0f / 256.0f);
    float e0 = __fadd_rn(lo, __fmul_rn(span, t0));
    float e1 = __fadd_rn(lo, __fmul_rn(span, t1));
    return __fmul_rn(__fadd_rn(e0, e1), 0.5f);
}

// ---------------- kernel 1: per-channel min/max (R8, unchanged) ------------
__global__ __launch_bounds__(TPB) void k_minmax(const float4* __restrict__ tgt) {
    const int c = blockIdx.y;
    const int tid = threadIdx.x;
    const float4* base = tgt + (size_t)c * NS4
                             + (size_t)blockIdx.x * (TPB * CHUNK) + tid;
    float4 V[CHUNK];
    #pragma unroll
    for (int k = 0; k < CHUNK; k++) V[k] = base[k * TPB];

    float lo0 = INFINITY, hi0 = -INFINITY, lo1 = INFINITY, hi1 = -INFINITY;
    #pragma unroll
    for (int k = 0; k < CHUNK; k++) {
        float l = fminf(fminf(V[k].x, V[k].y), fminf(V[k].z, V[k].w));
        float h = fmaxf(fmaxf(V[k].x, V[k].y), fmaxf(V[k].z, V[k].w));
        if (k & 1) { lo1 = fminf(lo1, l); hi1 = fmaxf(hi1, h); }
        else       { lo0 = fminf(lo0, l); hi0 = fmaxf(hi0, h); }
    }
    float lo = fminf(lo0, lo1), hi = fmaxf(hi0, hi1);
    for (int o = 16; o > 0; o >>= 1) {
        lo = fminf(lo, __shfl_down_sync(0xFFFFFFFFu, lo, o));
        hi = fmaxf(hi, __shfl_down_sync(0xFFFFFFFFu, hi, o));
    }
    __shared__ float slo[8], shi[8];
    int w = tid >> 5, lane = tid & 31;
    if (lane == 0) { slo[w] = lo; shi[w] = hi; }
    __syncthreads();
    if (tid == 0) {
        float l = slo[0], h = shi[0];
        for (int i = 1; i < 8; i++) { l = fminf(l, slo[i]); h = fmaxf(h, shi[i]); }
        atomicMin(&g_minkey[c], fkey(l));
        atomicMax(&g_maxkey[c], fkey(h));
    }
}

// -------- kernel 2: histogram (R8, unchanged) + fused Otsu -----------------
__global__ __launch_bounds__(TPB) void k_hist(const float4* __restrict__ tgt) {
    const int c = blockIdx.y;
    __shared__ unsigned int sh[8][NBINS];   // per-warp sub-histograms
    __shared__ float s_lo, s_span_safe, s_span_raw;
    int tid = threadIdx.x, w = tid >> 5;
    for (int i = tid; i < 8 * NBINS; i += TPB)
        ((unsigned int*)sh)[i] = 0u;
    if (tid == 0) {
        float lo = ikey(g_minkey[c]);
        float hi = ikey(g_maxkey[c]);
        float span = __fsub_rn(hi, lo);
        s_lo = lo;
        s_span_raw = span;
        s_span_safe = (span > 0.0f) ? span : 1.0f;
    }
    __syncthreads();
    const float lo = s_lo, span = s_span_safe;

    const float4* rtop = tgt + (size_t)c * NS4 + (NS4 - 1);
    const int bbase = blockIdx.x * (TPB * CHUNK * IT_H) + tid;
    #pragma unroll
    for (int it = 0; it < IT_H; it++) {
        float4 V[CHUNK];
        const int ibase = bbase + it * (TPB * CHUNK);
        #pragma unroll
        for (int k = 0; k < CHUNK; k++)        // 4 LDG.128 back-to-back
            V[k] = rtop[-(ibase + k * TPB)];
        #pragma unroll
        for (int k = 0; k < CHUNK; k++) {
            #pragma unroll
            for (int j = 0; j < 4; j++) {
                float x = (j == 0) ? V[k].x : (j == 1) ? V[k].y
                        : (j == 2) ? V[k].z : V[k].w;
                float q = __fmul_rn(__fdiv_rn(__fsub_rn(x, lo), span), 256.0f);
                int b = (int)q;
                b = min(max(b, 0), NBINS - 1);
                atomicAdd(&sh[w][b], 1u);
            }
        }
    }
    __syncthreads();
    {
        unsigned int s = 0;
        #pragma unroll
        for (int k = 0; k < 8; k++) s += sh[k][tid];
        if (s) atomicAdd(&g_hist[c][tid], s);
    }

    // ---- last block of this channel computes the Otsu threshold ----
    __threadfence();
    __shared__ bool is_last;
    if (tid == 0)
        is_last = (atomicAdd(&g_cnt_hist[c], 1u) == (unsigned)(BPC_H - 1));
    __syncthreads();
    if (!is_last) return;

    __shared__ float s_h[NBINS], s_hm[NBINS], s_ctr[NBINS];
    __shared__ float s_cs[NBINS], s_cm[NBINS];
    __shared__ float rv[NBINS]; __shared__ int ri[NBINS];

    const float span_raw = s_span_raw;
    float h   = (float)__ldcg(&g_hist[c][tid]);
    float ctr = bin_center(lo, span_raw, tid);
    s_h[tid] = h; s_ctr[tid] = ctr; s_hm[tid] = __fmul_rn(h, ctr);
    __syncthreads();

    if (tid == 0) {   // sequential fp32 cumsum (matches reference order)
        float cs = 0.0f, cm = 0.0f;
        #pragma unroll
        for (int i = 0; i < NBINS; i++) {
            cs = __fadd_rn(cs, s_h[i]);
            cm = __fadd_rn(cm, s_hm[i]);
            s_cs[i] = cs; s_cm[i] = cm;
        }
    }
    __syncthreads();
    const float total = s_cs[NBINS - 1];
    const float gmean = s_cm[NBINS - 1];

    float cs = s_cs[tid], cm = s_cm[tid];
    float A  = __fsub_rn(__fmul_rn(cm, total), __fmul_rn(gmean, cs));
    float dn = __fadd_rn(__fmul_rn(cs, __fsub_rn(total, cs)), 1e-10f);
    float iv = __fdiv_rn(__fmul_rn(A, A), dn);

    rv[tid] = iv; ri[tid] = tid;
    __syncthreads();
    for (int s = NBINS / 2; s > 0; s >>= 1) {   // argmax, first-index tie-break
        if (tid < s) {
            if (rv[tid + s] > rv[tid] ||
                (rv[tid + s] == rv[tid] && ri[tid + s] < ri[tid])) {
                rv[tid] = rv[tid + s]; ri[tid] = ri[tid + s];
            }
        }
        __syncthreads();
    }
    if (tid == 0)
        g_thr[c] = (span_raw > 0.0f) ? s_ctr[ri[0]] : lo;
}

// ---- kernel 3: fused main reductions (single wave, no dead tot) -----------
// NOTE: thr is a bin center < channel max (or == lo when span==0), so the
// mask always has >=1 element: the regular_mse fallback is unreachable and
// the total-sq-err accumulator is dead work -- removed.
__global__ __launch_bounds__(TPB, 7) void k_main(const float4* __restrict__ pred,
                                                 const float4* __restrict__ tgt,
                                                 float* __restrict__ out) {
    const int c = blockIdx.y;
    const int tid = threadIdx.x;
    const float thr = g_thr[c];
    const size_t base = (size_t)c * NS4
                      + (size_t)blockIdx.x * (TPB * CHUNK * IT_M) + tid;
    const float4* pb = pred + base;
    const float4* tb = tgt  + base;

    float msum0 = 0.f, int0 = 0.f, ss0 = 0.f;
    float msum1 = 0.f, int1 = 0.f, ss1 = 0.f;
    int fg = 0;

    #pragma unroll
    for (int it = 0; it < IT_M; it++) {
        float4 P[CHUNK], T[CHUNK];
        const int ioff = it * (TPB * CHUNK);
        #pragma unroll
        for (int k = 0; k < CHUNK; k++) {     // 8 LDG.128 back-to-back (MLP 8)
            P[k] = pb[ioff + k * TPB];
            T[k] = tb[ioff + k * TPB];
        }
        #pragma unroll
        for (int k = 0; k < CHUNK; k++) {
            #pragma unroll
            for (int j = 0; j < 4; j++) {
                float p = (j == 0) ? P[k].x : (j == 1) ? P[k].y
                        : (j == 2) ? P[k].z : P[k].w;
                float t = (j == 0) ? T[k].x : (j == 1) ? T[k].y
                        : (j == 2) ? T[k].z : T[k].w;
                bool m = (t >= thr);
                float d  = p - t;
                float se = d * d;
                float ax  = fabsf(p);
                float num = p - (-0.95f) * p;                 // 1.95*x
                float den = (-0.95f - (-1.9f) * ax) + 1.0f;   // 0.05 + 1.9|x|
                float sp  = __saturatef(__fdividef(num, den));
                float sem = m ? se : 0.0f;
                float spm = m ? sp : 0.0f;
                fg += m;
                if (k & 1) { msum1 += sem; ss1 += sp; int1 += spm; }
                else       { msum0 += sem; ss0 += sp; int0 += spm; }
            }
        }
    }
    float msum = msum0 + msum1;
    float inter = int0 + int1,  ssum = ss0 + ss1;

    for (int o = 16; o > 0; o >>= 1) {
        msum  += __shfl_down_sync(0xFFFFFFFFu, msum,  o);
        inter += __shfl_down_sync(0xFFFFFFFFu, inter, o);
        ssum  += __shfl_down_sync(0xFFFFFFFFu, ssum,  o);
        fg    += __shfl_down_sync(0xFFFFFFFFu, fg,    o);
    }
    __shared__ float  s0[8], s2[8], s3[8];
    __shared__ int    s4[8];
    int w = tid >> 5, lane = tid & 31;
    if (lane == 0) { s0[w]=msum; s2[w]=inter; s3[w]=ssum; s4[w]=fg; }
    __syncthreads();
    __shared__ bool is_last;
    if (tid == 0) {
        double a=0, cI=0, dS=0; long long f=0;
        #pragma unroll
        for (int k = 0; k < 8; k++) { a+=s0[k]; cI+=s2[k]; dS+=s3[k]; f+=s4[k]; }
        atomicAdd(&g_msum[c],  a);
        atomicAdd(&g_inter[c], cI);
        atomicAdd(&g_ssum[c],  dS);
        atomicAdd(&g_fg[c], (unsigned long long)f);
        __threadfence();
        is_last = (atomicAdd(&g_cnt_main, 1u) == (unsigned)(BPC_M * R - 1));
    }
    __syncthreads();
    if (!is_last) return;

    // ---- globally-last block: combine to scalar ----
    if (tid == 0) {
        double mse_sum = 0.0, dice_sum = 0.0;
        int nmask = 0;
        for (int ch = 0; ch < R; ch++) {
            double fgc = (double)__ldcg(&g_fg[ch]);
            // fg >= 1 always (see note above): has_fg branch only
            mse_sum += __ldcg(&g_msum[ch]) / (fgc + 1e-6);
            dice_sum += 1.0 - 2.0 * __ldcg(&g_inter[ch]) /
                                    (__ldcg(&g_ssum[ch]) + fgc + 1e-6);
            nmask++;
        }
        double masked_mse = mse_sum / (double)R;
        double dice = (nmask > 0) ? dice_sum / (double)nmask : 0.0;
        out[0] = (float)(0.5 * masked_mse + 0.5 * dice);
    }
    __syncthreads();   // combine reads done before reset below

    // ---- self-clean scratch back to static-init state for next replay ----
    for (int i = tid; i < R * NBINS; i += TPB)
        ((unsigned int*)g_hist)[i] = 0u;
    if (tid < R) {
        g_minkey[tid] = 0xFFFFFFFFu;
        g_maxkey[tid] = 0u;
        g_msum[tid] = 0.0; g_inter[tid] = 0.0; g_ssum[tid] = 0.0;
        g_fg[tid] = 0ull;
        g_thr[tid] = 0.0f;
        g_cnt_hist[tid] = 0u;
    }
    if (tid == R) g_cnt_main = 0u;
}

// ---------------- launch ----------------
extern "C" void kernel_launch(void* const* d_in, const int* in_sizes, int n_in,
                              void* d_out, int out_size) {
    const float4* pred = (const float4*)d_in[0];
    const float4* tgt  = (const float4*)d_in[1];
    float* out = (float*)d_out;

    k_minmax<<<dim3(BPC_MM, R), TPB>>>(tgt);
    k_hist  <<<dim3(BPC_H,  R), TPB>>>(tgt);
    k_main  <<<dim3(BPC_M,  R), TPB>>>(pred, tgt, out);
}